// round 10
// baseline (speedup 1.0000x reference)
#include <cuda_runtime.h>
#include <cstdint>

// SE(3) exp(xi) @ poses_init:
//   loads:  cp.async.bulk (TMA-class, bypasses L1, ~2 instr/tile) -> SMEM
//   reads:  conflict-free rotated LDS
//   stores: direct STG.128 .cs (fire-and-forget, no staging/fence/wait)
#define EPS_THETA 1e-6f
#define TILE 256
#define THREADS 256

#define XI_BYTES   (TILE * 6 * 4)    // 6144
#define POSE_BYTES (TILE * 16 * 4)   // 16384

struct __align__(16) SmemLayout {
    float  xi[TILE * 6];             // 6144 B
    float4 pose[TILE * 4];           // 16384 B
    unsigned long long mbar;
};

__device__ __forceinline__ uint32_t s2u(const void* p) {
    return (uint32_t)__cvta_generic_to_shared(p);
}
__device__ __forceinline__ void mbar_init(uint32_t mbar, uint32_t count) {
    asm volatile("mbarrier.init.shared.b64 [%0], %1;" :: "r"(mbar), "r"(count) : "memory");
}
__device__ __forceinline__ void mbar_expect_tx(uint32_t mbar, uint32_t bytes) {
    asm volatile("mbarrier.arrive.expect_tx.shared.b64 _, [%0], %1;"
                 :: "r"(mbar), "r"(bytes) : "memory");
}
__device__ __forceinline__ void mbar_wait(uint32_t mbar, uint32_t parity) {
    asm volatile(
        "{\n\t"
        ".reg .pred P1;\n\t"
        "WAIT_LOOP_%=:\n\t"
        "mbarrier.try_wait.parity.acquire.cta.shared::cta.b64 P1, [%0], %1, 0x989680;\n\t"
        "@P1 bra.uni WAIT_DONE_%=;\n\t"
        "bra.uni WAIT_LOOP_%=;\n\t"
        "WAIT_DONE_%=:\n\t"
        "}"
        :: "r"(mbar), "r"(parity) : "memory");
}
__device__ __forceinline__ void bulk_load(uint32_t dst_smem, const void* src_gmem,
                                          uint32_t bytes, uint32_t mbar) {
    asm volatile(
        "cp.async.bulk.shared::cluster.global.mbarrier::complete_tx::bytes [%0], [%1], %2, [%3];"
        :: "r"(dst_smem), "l"(src_gmem), "r"(bytes), "r"(mbar) : "memory");
}

__device__ __forceinline__ float4 f4_fma(float a, float4 x, float4 acc) {
    acc.x = fmaf(a, x.x, acc.x);
    acc.y = fmaf(a, x.y, acc.y);
    acc.z = fmaf(a, x.z, acc.z);
    acc.w = fmaf(a, x.w, acc.w);
    return acc;
}
__device__ __forceinline__ float4 f4_scale(float a, float4 x) {
    return make_float4(a * x.x, a * x.y, a * x.z, a * x.w);
}

// Branchless Rodrigues without normalization:
// R = I + A*W + B*W^2, W = skew(w), W^2 = w w^T - theta^2 I
__device__ __forceinline__ void se3_rows(
    float tx, float ty, float tz, float wx, float wy, float wz,
    float4 p0, float4 p1, float4 p2, float4 p3,
    float4& o0, float4& o1, float4& o2)
{
    float theta2 = wx*wx + wy*wy + wz*wz;
    float theta  = sqrtf(theta2);
    bool  small  = theta < EPS_THETA;
    float A = small ? 1.0f : sinf(theta) / theta;
    float B = small ? 0.0f : (1.0f - cosf(theta)) / theta2;

    float R00 = 1.0f + B * (wx*wx - theta2);
    float R11 = 1.0f + B * (wy*wy - theta2);
    float R22 = 1.0f + B * (wz*wz - theta2);
    float bxy = B*wx*wy, bxz = B*wx*wz, byz = B*wy*wz;
    float awx = A*wx, awy = A*wy, awz = A*wz;
    float R01 = bxy - awz, R02 = bxz + awy;
    float R10 = bxy + awz, R12 = byz - awx;
    float R20 = bxz - awy, R21 = byz + awx;

    o0 = f4_scale(R00, p0);
    o0 = f4_fma(R01, p1, o0); o0 = f4_fma(R02, p2, o0); o0 = f4_fma(tx, p3, o0);
    o1 = f4_scale(R10, p0);
    o1 = f4_fma(R11, p1, o1); o1 = f4_fma(R12, p2, o1); o1 = f4_fma(ty, p3, o1);
    o2 = f4_scale(R20, p0);
    o2 = f4_fma(R21, p1, o2); o2 = f4_fma(R22, p2, o2); o2 = f4_fma(tz, p3, o2);
}

__global__ void __launch_bounds__(THREADS) se3_tma_stg_kernel(
    const float*  __restrict__ xi,      // [N, 6]
    const float4* __restrict__ poses,   // [N, 4] rows
    float4*       __restrict__ out,     // [N, 4] rows
    int n)
{
    __shared__ SmemLayout sm;
    int tid  = threadIdx.x;
    long base = (long)blockIdx.x * TILE;
    int cnt  = (int)min((long)TILE, (long)n - base);

    if (cnt == TILE) {
        uint32_t mbar = s2u(&sm.mbar);
        if (tid == 0) mbar_init(mbar, 1);
        __syncthreads();
        if (tid == 0) {
            mbar_expect_tx(mbar, XI_BYTES + POSE_BYTES);
            bulk_load(s2u(sm.xi),   xi    + base * 6, XI_BYTES,   mbar);
            bulk_load(s2u(sm.pose), poses + base * 4, POSE_BYTES, mbar);
        }
        mbar_wait(mbar, 0);

        // xi: LDS.64 x3, 24B stride -> conflict-free
        const float2* xr = reinterpret_cast<const float2*>(&sm.xi[tid * 6]);
        float2 a0 = xr[0], a1 = xr[1], a2 = xr[2];

        // pose: rotated row order -> each LDS.128 phase hits 8 distinct banks
        float4 p[4];
        int rot = (tid >> 1) & 3;
#pragma unroll
        for (int k = 0; k < 4; k++) {
            int r = (k + rot) & 3;
            p[r] = sm.pose[tid * 4 + r];
        }

        float4 o0, o1, o2;
        se3_rows(a0.x, a0.y, a1.x, a1.y, a2.x, a2.y, p[0], p[1], p[2], p[3], o0, o1, o2);

        float4* O = out + (base + tid) * 4;
        __stcs(O + 0, o0);
        __stcs(O + 1, o1);
        __stcs(O + 2, o2);
        __stcs(O + 3, p[3]);
    } else {
        // tail tile: direct global path
        for (int i = tid; i < cnt; i += THREADS) {
            long g = base + i;
            const float2* xr = reinterpret_cast<const float2*>(xi + g * 6);
            float2 a0 = xr[0], a1 = xr[1], a2 = xr[2];
            const float4* P = poses + g * 4;
            float4 p0 = P[0], p1 = P[1], p2 = P[2], p3 = P[3];
            float4 o0, o1, o2;
            se3_rows(a0.x, a0.y, a1.x, a1.y, a2.x, a2.y, p0, p1, p2, p3, o0, o1, o2);
            float4* O = out + g * 4;
            O[0] = o0; O[1] = o1; O[2] = o2; O[3] = p3;
        }
    }
}

extern "C" void kernel_launch(void* const* d_in, const int* in_sizes, int n_in,
                              void* d_out, int out_size) {
    const float*  xi    = (const float*)d_in[0];   // [N,6]
    const float4* poses = (const float4*)d_in[1];  // [N,4,4] rows of float4
    float4*       out   = (float4*)d_out;
    int n = in_sizes[0] / 6;
    int blocks = (n + TILE - 1) / TILE;
    se3_tma_stg_kernel<<<blocks, THREADS>>>(xi, poses, out, n);
}

// round 11
// speedup vs baseline: 1.8207x; 1.8207x over previous
#include <cuda_runtime.h>
#include <cstdint>

// SE(3) exp(xi) @ poses_init:
//   loads:  cp.async.bulk (TMA-class, bypasses L1, ~2 instr/tile) -> SMEM
//   reads:  static named-register LDS (NO dynamic register indexing --
//           R10's rotated p[r] forced local-memory spills: L1 77%, 105us)
//   stores: direct STG.128 .cs (fire-and-forget, no staging/fence/wait)
#define EPS_THETA 1e-6f
#define TILE 256
#define THREADS 256

#define XI_BYTES   (TILE * 6 * 4)    // 6144
#define POSE_BYTES (TILE * 16 * 4)   // 16384

struct __align__(16) SmemLayout {
    float  xi[TILE * 6];             // 6144 B
    float4 pose[TILE * 4];           // 16384 B
    unsigned long long mbar;
};

__device__ __forceinline__ uint32_t s2u(const void* p) {
    return (uint32_t)__cvta_generic_to_shared(p);
}
__device__ __forceinline__ void mbar_init(uint32_t mbar, uint32_t count) {
    asm volatile("mbarrier.init.shared.b64 [%0], %1;" :: "r"(mbar), "r"(count) : "memory");
}
__device__ __forceinline__ void mbar_expect_tx(uint32_t mbar, uint32_t bytes) {
    asm volatile("mbarrier.arrive.expect_tx.shared.b64 _, [%0], %1;"
                 :: "r"(mbar), "r"(bytes) : "memory");
}
__device__ __forceinline__ void mbar_wait(uint32_t mbar, uint32_t parity) {
    asm volatile(
        "{\n\t"
        ".reg .pred P1;\n\t"
        "WAIT_LOOP_%=:\n\t"
        "mbarrier.try_wait.parity.acquire.cta.shared::cta.b64 P1, [%0], %1, 0x989680;\n\t"
        "@P1 bra.uni WAIT_DONE_%=;\n\t"
        "bra.uni WAIT_LOOP_%=;\n\t"
        "WAIT_DONE_%=:\n\t"
        "}"
        :: "r"(mbar), "r"(parity) : "memory");
}
__device__ __forceinline__ void bulk_load(uint32_t dst_smem, const void* src_gmem,
                                          uint32_t bytes, uint32_t mbar) {
    asm volatile(
        "cp.async.bulk.shared::cluster.global.mbarrier::complete_tx::bytes [%0], [%1], %2, [%3];"
        :: "r"(dst_smem), "l"(src_gmem), "r"(bytes), "r"(mbar) : "memory");
}

__device__ __forceinline__ float4 f4_fma(float a, float4 x, float4 acc) {
    acc.x = fmaf(a, x.x, acc.x);
    acc.y = fmaf(a, x.y, acc.y);
    acc.z = fmaf(a, x.z, acc.z);
    acc.w = fmaf(a, x.w, acc.w);
    return acc;
}
__device__ __forceinline__ float4 f4_scale(float a, float4 x) {
    return make_float4(a * x.x, a * x.y, a * x.z, a * x.w);
}

// Branchless Rodrigues without normalization:
// R = I + A*W + B*W^2, W = skew(w), W^2 = w w^T - theta^2 I
__device__ __forceinline__ void se3_rows(
    float tx, float ty, float tz, float wx, float wy, float wz,
    float4 p0, float4 p1, float4 p2, float4 p3,
    float4& o0, float4& o1, float4& o2)
{
    float theta2 = wx*wx + wy*wy + wz*wz;
    float theta  = sqrtf(theta2);
    bool  small  = theta < EPS_THETA;
    float A = small ? 1.0f : sinf(theta) / theta;
    float B = small ? 0.0f : (1.0f - cosf(theta)) / theta2;

    float R00 = 1.0f + B * (wx*wx - theta2);
    float R11 = 1.0f + B * (wy*wy - theta2);
    float R22 = 1.0f + B * (wz*wz - theta2);
    float bxy = B*wx*wy, bxz = B*wx*wz, byz = B*wy*wz;
    float awx = A*wx, awy = A*wy, awz = A*wz;
    float R01 = bxy - awz, R02 = bxz + awy;
    float R10 = bxy + awz, R12 = byz - awx;
    float R20 = bxz - awy, R21 = byz + awx;

    o0 = f4_scale(R00, p0);
    o0 = f4_fma(R01, p1, o0); o0 = f4_fma(R02, p2, o0); o0 = f4_fma(tx, p3, o0);
    o1 = f4_scale(R10, p0);
    o1 = f4_fma(R11, p1, o1); o1 = f4_fma(R12, p2, o1); o1 = f4_fma(ty, p3, o1);
    o2 = f4_scale(R20, p0);
    o2 = f4_fma(R21, p1, o2); o2 = f4_fma(R22, p2, o2); o2 = f4_fma(tz, p3, o2);
}

__global__ void __launch_bounds__(THREADS) se3_tma_stg_kernel(
    const float*  __restrict__ xi,      // [N, 6]
    const float4* __restrict__ poses,   // [N, 4] rows
    float4*       __restrict__ out,     // [N, 4] rows
    int n)
{
    __shared__ SmemLayout sm;
    int tid  = threadIdx.x;
    long base = (long)blockIdx.x * TILE;
    int cnt  = (int)min((long)TILE, (long)n - base);

    if (cnt == TILE) {
        uint32_t mbar = s2u(&sm.mbar);
        if (tid == 0) mbar_init(mbar, 1);
        __syncthreads();
        if (tid == 0) {
            mbar_expect_tx(mbar, XI_BYTES + POSE_BYTES);
            bulk_load(s2u(sm.xi),   xi    + base * 6, XI_BYTES,   mbar);
            bulk_load(s2u(sm.pose), poses + base * 4, POSE_BYTES, mbar);
        }
        mbar_wait(mbar, 0);

        // xi: LDS.64 x3, 24B stride -> conflict-free
        const float2* xr = reinterpret_cast<const float2*>(&sm.xi[tid * 6]);
        float2 a0 = xr[0], a1 = xr[1], a2 = xr[2];

        // pose rows: static named registers (4-way bank conflict is hideable;
        // dynamic-index "fix" was the R10 disaster)
        float4 p0 = sm.pose[tid * 4 + 0];
        float4 p1 = sm.pose[tid * 4 + 1];
        float4 p2 = sm.pose[tid * 4 + 2];
        float4 p3 = sm.pose[tid * 4 + 3];

        float4 o0, o1, o2;
        se3_rows(a0.x, a0.y, a1.x, a1.y, a2.x, a2.y, p0, p1, p2, p3, o0, o1, o2);

        float4* O = out + (base + tid) * 4;
        __stcs(O + 0, o0);
        __stcs(O + 1, o1);
        __stcs(O + 2, o2);
        __stcs(O + 3, p3);
    } else {
        // tail tile: direct global path
        for (int i = tid; i < cnt; i += THREADS) {
            long g = base + i;
            const float2* xr = reinterpret_cast<const float2*>(xi + g * 6);
            float2 a0 = xr[0], a1 = xr[1], a2 = xr[2];
            const float4* P = poses + g * 4;
            float4 p0 = P[0], p1 = P[1], p2 = P[2], p3 = P[3];
            float4 o0, o1, o2;
            se3_rows(a0.x, a0.y, a1.x, a1.y, a2.x, a2.y, p0, p1, p2, p3, o0, o1, o2);
            float4* O = out + g * 4;
            O[0] = o0; O[1] = o1; O[2] = o2; O[3] = p3;
        }
    }
}

extern "C" void kernel_launch(void* const* d_in, const int* in_sizes, int n_in,
                              void* d_out, int out_size) {
    const float*  xi    = (const float*)d_in[0];   // [N,6]
    const float4* poses = (const float4*)d_in[1];  // [N,4,4] rows of float4
    float4*       out   = (float4*)d_out;
    int n = in_sizes[0] / 6;
    int blocks = (n + TILE - 1) / TILE;
    se3_tma_stg_kernel<<<blocks, THREADS>>>(xi, poses, out, n);
}

// round 15
// speedup vs baseline: 1.9502x; 1.0711x over previous
#include <cuda_runtime.h>

// SE(3) exp(xi) @ poses_init, 2 poses per thread (split-grid pairing:
// i0 = t, i1 = t + H) — R3's proven memory pattern — with a slimmed
// compute core: branchless Rodrigues (no normalization) and hardware
// MUFU __sinf/__cosf (theta ~0.17; abs err ~1e-6 << 1e-3 tolerance).
#define EPS_THETA 1e-6f

__device__ __forceinline__ float4 f4_fma(float a, float4 x, float4 acc) {
    acc.x = fmaf(a, x.x, acc.x);
    acc.y = fmaf(a, x.y, acc.y);
    acc.z = fmaf(a, x.z, acc.z);
    acc.w = fmaf(a, x.w, acc.w);
    return acc;
}
__device__ __forceinline__ float4 f4_scale(float a, float4 x) {
    return make_float4(a * x.x, a * x.y, a * x.z, a * x.w);
}

// R = I + A*W + B*W^2, W = skew(w), W^2 = w w^T - theta^2 I
// small: A=1, B=0  (matches reference R_small = I + skew(omega))
__device__ __forceinline__ void se3_rows(
    float tx, float ty, float tz, float wx, float wy, float wz,
    float4 p0, float4 p1, float4 p2, float4 p3,
    float4& o0, float4& o1, float4& o2)
{
    float theta2 = wx*wx + wy*wy + wz*wz;
    float theta  = sqrtf(theta2);
    bool  small  = theta < EPS_THETA;
    float s  = __sinf(theta);
    float c1 = 1.0f - __cosf(theta);
    float A = small ? 1.0f : s  / theta;
    float B = small ? 0.0f : c1 / theta2;

    float R00 = 1.0f + B * (wx*wx - theta2);
    float R11 = 1.0f + B * (wy*wy - theta2);
    float R22 = 1.0f + B * (wz*wz - theta2);
    float bxy = B*wx*wy, bxz = B*wx*wz, byz = B*wy*wz;
    float awx = A*wx, awy = A*wy, awz = A*wz;
    float R01 = bxy - awz, R02 = bxz + awy;
    float R10 = bxy + awz, R12 = byz - awx;
    float R20 = bxz - awy, R21 = byz + awx;

    o0 = f4_scale(R00, p0);
    o0 = f4_fma(R01, p1, o0); o0 = f4_fma(R02, p2, o0); o0 = f4_fma(tx, p3, o0);
    o1 = f4_scale(R10, p0);
    o1 = f4_fma(R11, p1, o1); o1 = f4_fma(R12, p2, o1); o1 = f4_fma(ty, p3, o1);
    o2 = f4_scale(R20, p0);
    o2 = f4_fma(R21, p1, o2); o2 = f4_fma(R22, p2, o2); o2 = f4_fma(tz, p3, o2);
}

__global__ void __launch_bounds__(256) se3_compose2f_kernel(
    const float*  __restrict__ xi,      // [N, 6]
    const float4* __restrict__ poses,   // [N, 4] rows of float4
    float4*       __restrict__ out,     // [N, 4] rows of float4
    int H, int n)
{
    int t = blockIdx.x * blockDim.x + threadIdx.x;
    if (t >= H) return;
    int i0 = t;
    int i1 = t + H;
    bool has1 = (i1 < n);

    // ---- front-batched loads (maximize MLP) ----
    const float2* xa = reinterpret_cast<const float2*>(xi + (size_t)i0 * 6);
    float2 a0 = __ldcs(xa + 0);
    float2 a1 = __ldcs(xa + 1);
    float2 a2 = __ldcs(xa + 2);

    const float2* xb = reinterpret_cast<const float2*>(xi + (size_t)i1 * 6);
    float2 b0, b1, b2;
    if (has1) { b0 = __ldcs(xb + 0); b1 = __ldcs(xb + 1); b2 = __ldcs(xb + 2); }

    const float4* Pa = poses + (size_t)i0 * 4;
    float4 pa0 = __ldcs(Pa + 0);
    float4 pa1 = __ldcs(Pa + 1);
    float4 pa2 = __ldcs(Pa + 2);
    float4 pa3 = __ldcs(Pa + 3);

    const float4* Pb = poses + (size_t)i1 * 4;
    float4 pb0, pb1, pb2, pb3;
    if (has1) {
        pb0 = __ldcs(Pb + 0);
        pb1 = __ldcs(Pb + 1);
        pb2 = __ldcs(Pb + 2);
        pb3 = __ldcs(Pb + 3);
    }

    // ---- pose 0 ----
    {
        float4 o0, o1, o2;
        se3_rows(a0.x, a0.y, a1.x, a1.y, a2.x, a2.y,
                 pa0, pa1, pa2, pa3, o0, o1, o2);
        float4* O = out + (size_t)i0 * 4;
        __stcs(O + 0, o0);
        __stcs(O + 1, o1);
        __stcs(O + 2, o2);
        __stcs(O + 3, pa3);
    }

    // ---- pose 1 ----
    if (has1) {
        float4 o0, o1, o2;
        se3_rows(b0.x, b0.y, b1.x, b1.y, b2.x, b2.y,
                 pb0, pb1, pb2, pb3, o0, o1, o2);
        float4* O = out + (size_t)i1 * 4;
        __stcs(O + 0, o0);
        __stcs(O + 1, o1);
        __stcs(O + 2, o2);
        __stcs(O + 3, pb3);
    }
}

extern "C" void kernel_launch(void* const* d_in, const int* in_sizes, int n_in,
                              void* d_out, int out_size) {
    const float*  xi    = (const float*)d_in[0];   // [N,6]
    const float4* poses = (const float4*)d_in[1];  // [N,4,4] rows of float4
    float4*       out   = (float4*)d_out;
    int n = in_sizes[0] / 6;
    int H = (n + 1) / 2;   // pairing: thread t -> poses t and t+H
    int threads = 256;
    int blocks = (H + threads - 1) / threads;
    se3_compose2f_kernel<<<blocks, threads>>>(xi, poses, out, H, n);
}